// round 13
// baseline (speedup 1.0000x reference)
#include <cuda_runtime.h>
#include <cuda_fp16.h>
#include <cstdint>

#define SEQ   2048
#define BATCH 2
#define NH    16
#define DH    64
#define DM    1024
#define MTOT  (BATCH*SEQ)   // 4096 rows

// fp16 scratch (device globals: no allocation allowed in kernel_launch)
__device__ __half h_x [(size_t)MTOT * DM];
__device__ __half h_q [(size_t)MTOT * DM];
__device__ __half h_k [(size_t)MTOT * DM];
__device__ __half h_v [(size_t)MTOT * DM];
__device__ __half h_z [(size_t)MTOT * DM];
__device__ __half h_wq[(size_t)DM * DM];
__device__ __half h_wk[(size_t)DM * DM];
__device__ __half h_wv[(size_t)DM * DM];
__device__ __half h_wo[(size_t)DM * DM];

// ===========================================================================
// helpers
// ===========================================================================
__device__ __forceinline__ void mma_f16(float* d, const unsigned* a, const unsigned* b) {
    asm volatile("mma.sync.aligned.m16n8k16.row.col.f32.f16.f16.f32 "
        "{%0,%1,%2,%3}, {%4,%5,%6,%7}, {%8,%9}, {%0,%1,%2,%3};"
        : "+f"(d[0]), "+f"(d[1]), "+f"(d[2]), "+f"(d[3])
        : "r"(a[0]), "r"(a[1]), "r"(a[2]), "r"(a[3]), "r"(b[0]), "r"(b[1]));
}

__device__ __forceinline__ unsigned pack_h2(float lo, float hi) {
    unsigned r;
    asm("cvt.rn.f16x2.f32 %0, %1, %2;" : "=r"(r) : "f"(hi), "f"(lo));
    return r;
}

__device__ __forceinline__ unsigned smem_u32(const void* p) {
    unsigned r;
    asm("{ .reg .u64 t; cvta.to.shared.u64 t, %1; cvt.u32.u64 %0, t; }"
        : "=r"(r) : "l"(p));
    return r;
}

__device__ __forceinline__ void cp16(unsigned dst, const void* src) {
    asm volatile("cp.async.cg.shared.global [%0], [%1], 16;" :: "r"(dst), "l"(src));
}
#define CP_COMMIT()  asm volatile("cp.async.commit_group;" ::: "memory")
#define CP_WAIT(n)   asm volatile("cp.async.wait_group %0;" :: "n"(n) : "memory")

// ===========================================================================
// prep kernels
// ===========================================================================
// fp32 -> fp16, 16 elems/thread (4 independent float4 loads: MLP=4)
__global__ __launch_bounds__(256) void convx_kernel(
    const float* __restrict__ X, __half* __restrict__ Y)
{
    const size_t i = ((size_t)blockIdx.x * 256 + threadIdx.x) * 16;
    float4 v0 = *(const float4*)&X[i];
    float4 v1 = *(const float4*)&X[i + 4];
    float4 v2 = *(const float4*)&X[i + 8];
    float4 v3 = *(const float4*)&X[i + 12];
    uint4 ua = { pack_h2(v0.x, v0.y), pack_h2(v0.z, v0.w),
                 pack_h2(v1.x, v1.y), pack_h2(v1.z, v1.w) };
    uint4 ub = { pack_h2(v2.x, v2.y), pack_h2(v2.z, v2.w),
                 pack_h2(v3.x, v3.y), pack_h2(v3.z, v3.w) };
    *(uint4*)&Y[i] = ua;
    *(uint4*)&Y[i + 8] = ub;
}

// fused QKV weight transpose+convert: z = mat*16 + head, mat in {Q,K,V}
__global__ __launch_bounds__(256) void tconv_qkv_kernel(
    const float* __restrict__ WQ, const float* __restrict__ WK,
    const float* __restrict__ WV,
    __half* __restrict__ YQ, __half* __restrict__ YK, __half* __restrict__ YV)
{
    __shared__ float t[32][33];
    const int mat = blockIdx.z >> 4, head = blockIdx.z & 15;
    const float* Xb = ((mat == 0) ? WQ : (mat == 1) ? WK : WV)
                      + (size_t)head * DM * DH;
    __half* Yb = ((mat == 0) ? YQ : (mat == 1) ? YK : YV)
                 + (size_t)head * DH * DM;
    const float scale = (mat == 0) ? 0.125f : 1.f;
    const int r0 = blockIdx.x * 32, c0 = blockIdx.y * 32;
    const int tx = threadIdx.x, ty = threadIdx.y;
    #pragma unroll
    for (int i = ty; i < 32; i += 8)
        t[i][tx] = Xb[(size_t)(r0 + i) * DH + c0 + tx];
    __syncthreads();
    #pragma unroll
    for (int i = ty; i < 32; i += 8)
        Yb[(size_t)(c0 + i) * DM + r0 + tx] = __float2half_rn(t[tx][i] * scale);
}

// single-matrix transpose+convert (W_O [1024][1024])
__global__ __launch_bounds__(256) void tconv_kernel(
    const float* __restrict__ X, __half* __restrict__ Y, int R, int C)
{
    __shared__ float t[32][33];
    const int r0 = blockIdx.x * 32, c0 = blockIdx.y * 32;
    const int tx = threadIdx.x, ty = threadIdx.y;
    #pragma unroll
    for (int i = ty; i < 32; i += 8)
        t[i][tx] = X[(size_t)(r0 + i) * C + c0 + tx];
    __syncthreads();
    #pragma unroll
    for (int i = ty; i < 32; i += 8)
        Y[(size_t)(c0 + i) * R + r0 + tx] = __float2half_rn(t[tx][i]);
}

// ===========================================================================
// fp16 tensor GEMM core: KCH=64, 2-stage cp.async pipeline.
//   C = A @ Wt[n][k] + bias*bscale
// Smem rows: 64 halfs data + pad, stride 36 words. Fragment read bank =
// (36g + tig) mod 32 = 4g + tig: conflict-free. 4 k-steps per chunk, 16
// chunks, barriers halved vs KCH=32. Smem total 73728 B (2 CTAs/SM ok).
// ===========================================================================
#define BM 128
#define BN 128
#define KCH 64             // halfs per k-chunk
#define NCHUNK (DM / KCH)  // 16
#define GSTW 36            // row stride in words
#define TOFFW 4608         // words per tile (128*36)
#define GEMM_SMEM 73728

template<int OUTF>
__device__ __forceinline__ void gemm_body(
    const __half* __restrict__ A, const __half* __restrict__ Wt,
    const float* __restrict__ bias, void* __restrict__ Cv, float bscale,
    unsigned* smemw, int m0, int n0)
{
    const unsigned sbase = smem_u32(smemw);
    const int tid = threadIdx.x;
    const int wid = tid >> 5, lane = tid & 31;
    const int g = lane >> 2, tig = lane & 3;
    const int warp_m = wid & 1, warp_n = wid >> 1;

    const int row = tid >> 1;            // 0..127
    const int hc  = (tid & 1) * 32;      // half offset within 64-half chunk
    const __half* Aptr = A  + (size_t)(m0 + row) * DM + hc;
    const __half* Bptr = Wt + (size_t)(n0 + row) * DM + hc;
    const unsigned aDst = sbase + (row * GSTW + (tid & 1) * 16) * 4;
    const unsigned bDst = aDst + 2 * TOFFW * 4;

    float acc[4][4][4];
    #pragma unroll
    for (int mt = 0; mt < 4; mt++)
        #pragma unroll
        for (int nt = 0; nt < 4; nt++)
            #pragma unroll
            for (int i = 0; i < 4; i++) acc[mt][nt][i] = 0.f;

    auto stage = [&](int c, int buf) {
        const __half* ap = Aptr + c * KCH;
        const __half* bp = Bptr + c * KCH;
        const unsigned ad = aDst + buf * (TOFFW * 4);
        const unsigned bd = bDst + buf * (TOFFW * 4);
        #pragma unroll
        for (int f = 0; f < 4; f++) {
            cp16(ad + f * 16, ap + f * 8);
            cp16(bd + f * 16, bp + f * 8);
        }
    };

    stage(0, 0); CP_COMMIT();

    for (int c = 0; c < NCHUNK; c++) {
        if (c + 1 < NCHUNK) { stage(c + 1, (c + 1) & 1); CP_COMMIT(); CP_WAIT(1); }
        else                { CP_WAIT(0); }
        __syncthreads();

        const unsigned* Asb = smemw + (c & 1) * TOFFW;
        const unsigned* Bsb = smemw + 2 * TOFFW + (c & 1) * TOFFW;
        #pragma unroll
        for (int kk = 0; kk < 4; kk++) {
            unsigned af[4][4], bf[4][2];
            #pragma unroll
            for (int mt = 0; mt < 4; mt++) {
                const int rb = warp_m * 64 + mt * 16 + g;
                af[mt][0] = Asb[rb * GSTW + kk * 8 + tig];
                af[mt][1] = Asb[(rb + 8) * GSTW + kk * 8 + tig];
                af[mt][2] = Asb[rb * GSTW + kk * 8 + tig + 4];
                af[mt][3] = Asb[(rb + 8) * GSTW + kk * 8 + tig + 4];
            }
            #pragma unroll
            for (int nt = 0; nt < 4; nt++) {
                const int cb = warp_n * 32 + nt * 8 + g;
                bf[nt][0] = Bsb[cb * GSTW + kk * 8 + tig];
                bf[nt][1] = Bsb[cb * GSTW + kk * 8 + tig + 4];
            }
            #pragma unroll
            for (int mt = 0; mt < 4; mt++)
                #pragma unroll
                for (int nt = 0; nt < 4; nt++)
                    mma_f16(acc[mt][nt], af[mt], bf[nt]);
        }
        __syncthreads();
    }

    #pragma unroll
    for (int mt = 0; mt < 4; mt++) {
        const int r0 = m0 + warp_m * 64 + mt * 16 + g;
        #pragma unroll
        for (int nt = 0; nt < 4; nt++) {
            const int col = n0 + warp_n * 32 + nt * 8 + 2 * tig;
            const float bx = bias[col] * bscale, by = bias[col + 1] * bscale;
            if (OUTF) {
                float* C = (float*)Cv;
                float2 v0 = { acc[mt][nt][0] + bx, acc[mt][nt][1] + by };
                float2 v1 = { acc[mt][nt][2] + bx, acc[mt][nt][3] + by };
                *(float2*)&C[(size_t)r0 * DM + col] = v0;
                *(float2*)&C[(size_t)(r0 + 8) * DM + col] = v1;
            } else {
                __half* C = (__half*)Cv;
                *(unsigned*)&C[(size_t)r0 * DM + col] =
                    pack_h2(acc[mt][nt][0] + bx, acc[mt][nt][1] + by);
                *(unsigned*)&C[(size_t)(r0 + 8) * DM + col] =
                    pack_h2(acc[mt][nt][2] + bx, acc[mt][nt][3] + by);
            }
        }
    }
}

// fused QKV: blockIdx.z selects {Q, K, V}
__global__ __launch_bounds__(256, 2) void tc_gemm_qkv(
    const __half* __restrict__ A,
    const __half* __restrict__ W0, const __half* __restrict__ W1,
    const __half* __restrict__ W2,
    const float* __restrict__ b0, const float* __restrict__ b1,
    const float* __restrict__ b2,
    __half* __restrict__ C0, __half* __restrict__ C1, __half* __restrict__ C2)
{
    extern __shared__ __align__(16) unsigned smemw[];
    const int z = blockIdx.z;
    const __half* Wt = (z == 0) ? W0 : (z == 1) ? W1 : W2;
    const float* bias = (z == 0) ? b0 : (z == 1) ? b1 : b2;
    __half* C = (z == 0) ? C0 : (z == 1) ? C1 : C2;
    const float bscale = (z == 0) ? 0.125f : 1.f;
    gemm_body<0>(A, Wt, bias, C, bscale, smemw, blockIdx.y * BM, blockIdx.x * BN);
}

__global__ __launch_bounds__(256, 2) void tc_gemm_out(
    const __half* __restrict__ A, const __half* __restrict__ Wt,
    const float* __restrict__ bias, float* __restrict__ C)
{
    extern __shared__ __align__(16) unsigned smemw[];
    gemm_body<1>(A, Wt, bias, C, 1.f, smemw, blockIdx.y * BM, blockIdx.x * BN);
}

// ===========================================================================
// Flash attention, fp16, m16n8k16, double-buffered K/V pipeline (R11 proven).
// ===========================================================================
#define HST 72   // half stride per row
#define HSW 36   // word stride per row
#define KVBUF (64 * HST)   // halfs per buffer

__global__ __launch_bounds__(256) void flash_h(
    const __half* __restrict__ Q, const __half* __restrict__ K,
    const __half* __restrict__ V, __half* __restrict__ Z)
{
    __shared__ __align__(16) __half ks[2 * KVBUF];
    __shared__ __align__(16) __half vs[2 * KVBUF];
    const unsigned ksb = smem_u32(ks);

    const int tid = threadIdx.x;
    const int wid = tid >> 5, lane = tid & 31;
    const int g = lane >> 2, tig = lane & 3;
    const int qt = gridDim.x - 1 - blockIdx.x;       // heavy tiles first
    const int bh = blockIdx.y;
    const int b = bh >> 4, h = bh & 15;
    const size_t base = ((size_t)b * SEQ * NH + h) * DH;
    const int qrow0 = qt * 128 + wid * 16;

    const int srow = tid >> 2;          // staging row 0..63
    const int sc16 = (tid & 3) * 16;    // half offset within 64-half row
    const unsigned sdst = ksb + srow * 144 + (tid & 3) * 32;

    // ---- Q -> register A-fragments (pre-scaled fp16; 2 cp.async passes) ----
    unsigned aq[4][4];
    #pragma unroll
    for (int pass = 0; pass < 2; pass++) {
        const __half* qp = Q + base + (size_t)(qt * 128 + pass * 64 + srow) * DM + sc16;
        cp16(sdst, qp); cp16(sdst + 16, qp + 8);
        CP_COMMIT(); CP_WAIT(0);
        __syncthreads();
        if ((wid >> 2) == pass) {
            const unsigned* ksw = (const unsigned*)ks;
            const int r = (wid & 3) * 16 + g;
            #pragma unroll
            for (int kk = 0; kk < 4; kk++) {
                aq[kk][0] = ksw[r * HSW + kk * 8 + tig];
                aq[kk][1] = ksw[(r + 8) * HSW + kk * 8 + tig];
                aq[kk][2] = ksw[r * HSW + kk * 8 + tig + 4];
                aq[kk][3] = ksw[(r + 8) * HSW + kk * 8 + tig + 4];
            }
        }
        __syncthreads();
    }

    float m0 = -1e30f, m1 = -1e30f, l0 = 0.f, l1 = 0.f;
    float oacc[8][4];
    #pragma unroll
    for (int nt = 0; nt < 8; nt++)
        #pragma unroll
        for (int i = 0; i < 4; i++) oacc[nt][i] = 0.f;

    const int vkv = tid & 63;          // V staging row
    const int vd0 = (tid >> 6) * 16;   // V staging d group
    const int NKT = 2 * qt + 2;

    // prologue: tile 0 into buf 0
    {
        const __half* kp = K + base + (size_t)srow * DM + sc16;
        cp16(sdst, kp); cp16(sdst + 16, kp + 8);
        CP_COMMIT();
        uint4 v0 = *(const uint4*)&V[base + (size_t)vkv * DM + vd0];
        uint4 v1 = *(const uint4*)&V[base + (size_t)vkv * DM + vd0 + 8];
        const __half* hp0 = (const __half*)&v0;
        const __half* hp1 = (const __half*)&v1;
        #pragma unroll
        for (int j = 0; j < 8; j++) {
            vs[(vd0 + j) * HST + vkv] = hp0[j];
            vs[(vd0 + 8 + j) * HST + vkv] = hp1[j];
        }
        CP_WAIT(0);
        __syncthreads();
    }

    for (int kt = 0; kt < NKT; kt++) {
        const int ktb = kt * 64;
        const int buf = kt & 1, nbuf = buf ^ 1;
        uint4 pv0, pv1;
        const bool pre = (kt + 1 < NKT);
        if (pre) {
            const __half* kp = K + base + (size_t)(ktb + 64 + srow) * DM + sc16;
            const unsigned kd = sdst + nbuf * (KVBUF * 2);
            cp16(kd, kp); cp16(kd + 16, kp + 8);
            CP_COMMIT();
            pv0 = *(const uint4*)&V[base + (size_t)(ktb + 64 + vkv) * DM + vd0];
            pv1 = *(const uint4*)&V[base + (size_t)(ktb + 64 + vkv) * DM + vd0 + 8];
        }

        if (ktb <= qrow0 + 15) {
            const unsigned* ksw = (const unsigned*)(ks + buf * KVBUF);
            const unsigned* vsw = (const unsigned*)(vs + buf * KVBUF);

            // ---- S = Q K^T ----
            float sacc[8][4];
            #pragma unroll
            for (int nt = 0; nt < 8; nt++)
                #pragma unroll
                for (int i = 0; i < 4; i++) sacc[nt][i] = 0.f;

            #pragma unroll
            for (int kk = 0; kk < 4; kk++) {
                unsigned bf[8][2];
                #pragma unroll
                for (int nt = 0; nt < 8; nt++) {
                    bf[nt][0] = ksw[(nt * 8 + g) * HSW + kk * 8 + tig];
                    bf[nt][1] = ksw[(nt * 8 + g) * HSW + kk * 8 + tig + 4];
                }
                #pragma unroll
                for (int nt = 0; nt < 8; nt++)
                    mma_f16(sacc[nt], aq[kk], bf[nt]);
            }

            // ---- causal mask (diagonal tiles only) ----
            if (ktb + 63 > qrow0) {
                #pragma unroll
                for (int nt = 0; nt < 8; nt++) {
                    const int kv0 = ktb + nt * 8 + 2 * tig;
                    if (kv0     > qrow0 + g)     sacc[nt][0] = -1e30f;
                    if (kv0 + 1 > qrow0 + g)     sacc[nt][1] = -1e30f;
                    if (kv0     > qrow0 + g + 8) sacc[nt][2] = -1e30f;
                    if (kv0 + 1 > qrow0 + g + 8) sacc[nt][3] = -1e30f;
                }
            }

            // ---- online softmax ----
            float rm0 = -1e30f, rm1 = -1e30f;
            #pragma unroll
            for (int nt = 0; nt < 8; nt++) {
                rm0 = fmaxf(rm0, fmaxf(sacc[nt][0], sacc[nt][1]));
                rm1 = fmaxf(rm1, fmaxf(sacc[nt][2], sacc[nt][3]));
            }
            rm0 = fmaxf(rm0, __shfl_xor_sync(0xffffffffu, rm0, 1));
            rm0 = fmaxf(rm0, __shfl_xor_sync(0xffffffffu, rm0, 2));
            rm1 = fmaxf(rm1, __shfl_xor_sync(0xffffffffu, rm1, 1));
            rm1 = fmaxf(rm1, __shfl_xor_sync(0xffffffffu, rm1, 2));
            const float mn0 = fmaxf(m0, rm0), mn1 = fmaxf(m1, rm1);
            const float al0 = __expf(m0 - mn0), al1 = __expf(m1 - mn1);
            float rs0 = 0.f, rs1 = 0.f;
            #pragma unroll
            for (int nt = 0; nt < 8; nt++) {
                sacc[nt][0] = __expf(sacc[nt][0] - mn0); rs0 += sacc[nt][0];
                sacc[nt][1] = __expf(sacc[nt][1] - mn0); rs0 += sacc[nt][1];
                sacc[nt][2] = __expf(sacc[nt][2] - mn1); rs1 += sacc[nt][2];
                sacc[nt][3] = __expf(sacc[nt][3] - mn1); rs1 += sacc[nt][3];
            }
            rs0 += __shfl_xor_sync(0xffffffffu, rs0, 1);
            rs0 += __shfl_xor_sync(0xffffffffu, rs0, 2);
            rs1 += __shfl_xor_sync(0xffffffffu, rs1, 1);
            rs1 += __shfl_xor_sync(0xffffffffu, rs1, 2);
            l0 = l0 * al0 + rs0;  l1 = l1 * al1 + rs1;
            m0 = mn0;             m1 = mn1;
            #pragma unroll
            for (int nt = 0; nt < 8; nt++) {
                oacc[nt][0] *= al0; oacc[nt][1] *= al0;
                oacc[nt][2] *= al1; oacc[nt][3] *= al1;
            }

            // ---- O += P V : S C-fragment IS the A-fragment ----
            #pragma unroll
            for (int kk = 0; kk < 4; kk++) {
                unsigned ap[4];
                ap[0] = pack_h2(sacc[2*kk][0],   sacc[2*kk][1]);
                ap[1] = pack_h2(sacc[2*kk][2],   sacc[2*kk][3]);
                ap[2] = pack_h2(sacc[2*kk+1][0], sacc[2*kk+1][1]);
                ap[3] = pack_h2(sacc[2*kk+1][2], sacc[2*kk+1][3]);
                unsigned bf[8][2];
                #pragma unroll
                for (int nt = 0; nt < 8; nt++) {
                    bf[nt][0] = vsw[(nt * 8 + g) * HSW + kk * 8 + tig];
                    bf[nt][1] = vsw[(nt * 8 + g) * HSW + kk * 8 + tig + 4];
                }
                #pragma unroll
                for (int nt = 0; nt < 8; nt++)
                    mma_f16(oacc[nt], ap, bf[nt]);
            }
        }

        if (pre) {
            __half* vb = vs + nbuf * KVBUF;
            const __half* hp0 = (const __half*)&pv0;
            const __half* hp1 = (const __half*)&pv1;
            #pragma unroll
            for (int j = 0; j < 8; j++) {
                vb[(vd0 + j) * HST + vkv] = hp0[j];
                vb[(vd0 + 8 + j) * HST + vkv] = hp1[j];
            }
            CP_WAIT(0);
        }
        __syncthreads();
    }

    // ---- normalize + write z (fp16) ----
    const float i0 = 1.f / l0, i1 = 1.f / l1;
    #pragma unroll
    for (int nt = 0; nt < 8; nt++) {
        const int col = nt * 8 + 2 * tig;
        const int row = qrow0 + g;
        *(unsigned*)&Z[base + (size_t)row * DM + col] =
            pack_h2(oacc[nt][0] * i0, oacc[nt][1] * i0);
        *(unsigned*)&Z[base + (size_t)(row + 8) * DM + col] =
            pack_h2(oacc[nt][2] * i1, oacc[nt][3] * i1);
    }
}

// ---------------------------------------------------------------------------

extern "C" void kernel_launch(void* const* d_in, const int* in_sizes, int n_in,
                              void* d_out, int out_size)
{
    const float* x  = (const float*)d_in[0];
    const float* WQ = (const float*)d_in[1];
    const float* WK = (const float*)d_in[2];
    const float* WV = (const float*)d_in[3];
    const float* WO = (const float*)d_in[4];
    const float* bQ = (const float*)d_in[5];
    const float* bK = (const float*)d_in[6];
    const float* bV = (const float*)d_in[7];
    const float* bO = (const float*)d_in[8];
    float* out = (float*)d_out;

    __half *xh, *qh, *kh, *vh, *zh, *wqt, *wkt, *wvt, *wot;
    cudaGetSymbolAddress((void**)&xh,  h_x);
    cudaGetSymbolAddress((void**)&qh,  h_q);
    cudaGetSymbolAddress((void**)&kh,  h_k);
    cudaGetSymbolAddress((void**)&vh,  h_v);
    cudaGetSymbolAddress((void**)&zh,  h_z);
    cudaGetSymbolAddress((void**)&wqt, h_wq);
    cudaGetSymbolAddress((void**)&wkt, h_wk);
    cudaGetSymbolAddress((void**)&wvt, h_wv);
    cudaGetSymbolAddress((void**)&wot, h_wo);

    cudaFuncSetAttribute(tc_gemm_qkv, cudaFuncAttributeMaxDynamicSharedMemorySize, GEMM_SMEM);
    cudaFuncSetAttribute(tc_gemm_out, cudaFuncAttributeMaxDynamicSharedMemorySize, GEMM_SMEM);

    // prep: convert x (MLP=4); fused QKV weight transpose; WO transpose
    convx_kernel<<<(MTOT * DM) / 4096, 256>>>(x, xh);
    tconv_qkv_kernel<<<dim3(32, 2, 48), dim3(32, 8)>>>(WQ, WK, WV, wqt, wkt, wvt);
    tconv_kernel<<<dim3(32, 32, 1), dim3(32, 8)>>>(WO, wot, DM, DM);

    tc_gemm_qkv<<<dim3(DM / BN, MTOT / BM, 3), 256, GEMM_SMEM>>>(
        xh, wqt, wkt, wvt, bQ, bK, bV, qh, kh, vh);
    flash_h<<<dim3(SEQ / 128, BATCH * NH), 256>>>(qh, kh, vh, zh);
    tc_gemm_out<<<dim3(DM / BN, MTOT / BM), 256, GEMM_SMEM>>>(zh, wot, bO, out);
}

// round 14
// speedup vs baseline: 1.1188x; 1.1188x over previous
#include <cuda_runtime.h>
#include <cuda_fp16.h>
#include <cstdint>

#define SEQ   2048
#define BATCH 2
#define NH    16
#define DH    64
#define DM    1024
#define MTOT  (BATCH*SEQ)   // 4096 rows

// fp16 scratch (device globals: no allocation allowed in kernel_launch)
__device__ __half h_x [(size_t)MTOT * DM];
__device__ __half h_q [(size_t)MTOT * DM];
__device__ __half h_k [(size_t)MTOT * DM];
__device__ __half h_v [(size_t)MTOT * DM];
__device__ __half h_z [(size_t)MTOT * DM];
__device__ __half h_wq[(size_t)DM * DM];
__device__ __half h_wk[(size_t)DM * DM];
__device__ __half h_wv[(size_t)DM * DM];
__device__ __half h_wo[(size_t)DM * DM];

// ===========================================================================
// helpers
// ===========================================================================
__device__ __forceinline__ void mma_f16(float* d, const unsigned* a, const unsigned* b) {
    asm volatile("mma.sync.aligned.m16n8k16.row.col.f32.f16.f16.f32 "
        "{%0,%1,%2,%3}, {%4,%5,%6,%7}, {%8,%9}, {%0,%1,%2,%3};"
        : "+f"(d[0]), "+f"(d[1]), "+f"(d[2]), "+f"(d[3])
        : "r"(a[0]), "r"(a[1]), "r"(a[2]), "r"(a[3]), "r"(b[0]), "r"(b[1]));
}

#define LDSM4(r0, r1, r2, r3, addr) \
    asm volatile("ldmatrix.sync.aligned.m8n8.x4.shared.b16 {%0,%1,%2,%3}, [%4];" \
        : "=r"(r0), "=r"(r1), "=r"(r2), "=r"(r3) : "r"(addr))

__device__ __forceinline__ unsigned pack_h2(float lo, float hi) {
    unsigned r;
    asm("cvt.rn.f16x2.f32 %0, %1, %2;" : "=r"(r) : "f"(hi), "f"(lo));
    return r;
}

__device__ __forceinline__ unsigned smem_u32(const void* p) {
    unsigned r;
    asm("{ .reg .u64 t; cvta.to.shared.u64 t, %1; cvt.u32.u64 %0, t; }"
        : "=r"(r) : "l"(p));
    return r;
}

__device__ __forceinline__ void cp16(unsigned dst, const void* src) {
    asm volatile("cp.async.cg.shared.global [%0], [%1], 16;" :: "r"(dst), "l"(src));
}
#define CP_COMMIT()  asm volatile("cp.async.commit_group;" ::: "memory")
#define CP_WAIT(n)   asm volatile("cp.async.wait_group %0;" :: "n"(n) : "memory")

// ===========================================================================
// prep kernels (unchanged from R12)
// ===========================================================================
__global__ __launch_bounds__(256) void convx_kernel(
    const float* __restrict__ X, __half* __restrict__ Y)
{
    const size_t i = ((size_t)blockIdx.x * 256 + threadIdx.x) * 16;
    float4 v0 = *(const float4*)&X[i];
    float4 v1 = *(const float4*)&X[i + 4];
    float4 v2 = *(const float4*)&X[i + 8];
    float4 v3 = *(const float4*)&X[i + 12];
    uint4 ua = { pack_h2(v0.x, v0.y), pack_h2(v0.z, v0.w),
                 pack_h2(v1.x, v1.y), pack_h2(v1.z, v1.w) };
    uint4 ub = { pack_h2(v2.x, v2.y), pack_h2(v2.z, v2.w),
                 pack_h2(v3.x, v3.y), pack_h2(v3.z, v3.w) };
    *(uint4*)&Y[i] = ua;
    *(uint4*)&Y[i + 8] = ub;
}

__global__ __launch_bounds__(256) void tconv_qkv_kernel(
    const float* __restrict__ WQ, const float* __restrict__ WK,
    const float* __restrict__ WV,
    __half* __restrict__ YQ, __half* __restrict__ YK, __half* __restrict__ YV)
{
    __shared__ float t[32][33];
    const int mat = blockIdx.z >> 4, head = blockIdx.z & 15;
    const float* Xb = ((mat == 0) ? WQ : (mat == 1) ? WK : WV)
                      + (size_t)head * DM * DH;
    __half* Yb = ((mat == 0) ? YQ : (mat == 1) ? YK : YV)
                 + (size_t)head * DH * DM;
    const float scale = (mat == 0) ? 0.125f : 1.f;
    const int r0 = blockIdx.x * 32, c0 = blockIdx.y * 32;
    const int tx = threadIdx.x, ty = threadIdx.y;
    #pragma unroll
    for (int i = ty; i < 32; i += 8)
        t[i][tx] = Xb[(size_t)(r0 + i) * DH + c0 + tx];
    __syncthreads();
    #pragma unroll
    for (int i = ty; i < 32; i += 8)
        Yb[(size_t)(c0 + i) * DM + r0 + tx] = __float2half_rn(t[tx][i] * scale);
}

__global__ __launch_bounds__(256) void tconv_kernel(
    const float* __restrict__ X, __half* __restrict__ Y, int R, int C)
{
    __shared__ float t[32][33];
    const int r0 = blockIdx.x * 32, c0 = blockIdx.y * 32;
    const int tx = threadIdx.x, ty = threadIdx.y;
    #pragma unroll
    for (int i = ty; i < 32; i += 8)
        t[i][tx] = X[(size_t)(r0 + i) * C + c0 + tx];
    __syncthreads();
    #pragma unroll
    for (int i = ty; i < 32; i += 8)
        Y[(size_t)(c0 + i) * R + r0 + tx] = __float2half_rn(t[tx][i]);
}

// ===========================================================================
// fp16 tensor GEMM: KCH=32, 3-stage cp.async (R12 proven) + ldmatrix frags.
// Smem rows 32 halfs data, stride 20 words; 8 consecutive rows at stride 20
// cover all 32 banks exactly once -> LDSM conflict-free.
// ===========================================================================
#define BM 128
#define BN 128
#define KCH 32             // halfs per k-chunk
#define NCHUNK (DM / KCH)  // 32
#define GSTW 20            // row stride in words
#define TOFFW 2560         // words per tile (128*20)
#define GEMM_SMEM 61440

template<int OUTF>
__device__ __forceinline__ void gemm_body(
    const __half* __restrict__ A, const __half* __restrict__ Wt,
    const float* __restrict__ bias, void* __restrict__ Cv, float bscale,
    unsigned* smemw, int m0, int n0)
{
    const unsigned sbase = smem_u32(smemw);
    const int tid = threadIdx.x;
    const int wid = tid >> 5, lane = tid & 31;
    const int g = lane >> 2, tig = lane & 3;
    const int warp_m = wid & 1, warp_n = wid >> 1;
    const int lrow = lane & 7, quad = lane >> 3;

    const int row = tid >> 1;
    const int hc  = (tid & 1) * 16;
    const __half* Aptr = A  + (size_t)(m0 + row) * DM + hc;
    const __half* Bptr = Wt + (size_t)(n0 + row) * DM + hc;
    const unsigned aDst = sbase + (row * GSTW + (tid & 1) * 8) * 4;
    const unsigned bDst = aDst + 3 * TOFFW * 4;

    // per-lane ldmatrix byte offsets (relative to tile base + kk words)
    const unsigned aoffB = ((lrow + 8 * (quad & 1)) * GSTW + 4 * (quad >> 1)) * 4;
    const unsigned boffB = ((lrow + 8 * (quad >> 1)) * GSTW + 4 * (quad & 1)) * 4;

    float acc[4][4][4];
    #pragma unroll
    for (int mt = 0; mt < 4; mt++)
        #pragma unroll
        for (int nt = 0; nt < 4; nt++)
            #pragma unroll
            for (int i = 0; i < 4; i++) acc[mt][nt][i] = 0.f;

    auto stage = [&](int c, int buf) {
        const __half* ap = Aptr + c * KCH;
        const __half* bp = Bptr + c * KCH;
        const unsigned ad = aDst + buf * (TOFFW * 4);
        const unsigned bd = bDst + buf * (TOFFW * 4);
        cp16(ad, ap); cp16(ad + 16, ap + 8);
        cp16(bd, bp); cp16(bd + 16, bp + 8);
    };

    stage(0, 0); CP_COMMIT();
    stage(1, 1); CP_COMMIT();

    int buf = 0;
    for (int c = 0; c < NCHUNK; c++) {
        if (c + 2 < NCHUNK) { stage(c + 2, (c + 2) % 3); CP_COMMIT(); CP_WAIT(2); }
        else if (c + 1 < NCHUNK) { CP_WAIT(1); }
        else { CP_WAIT(0); }
        __syncthreads();

        const unsigned abase = sbase + buf * (TOFFW * 4);
        const unsigned bbase = abase + 3 * TOFFW * 4;
        #pragma unroll
        for (int kk = 0; kk < 2; kk++) {
            unsigned af[4][4], bf[4][2];
            #pragma unroll
            for (int mt = 0; mt < 4; mt++) {
                const unsigned ra = abase +
                    ((warp_m * 64 + mt * 16) * GSTW + kk * 8) * 4 + aoffB;
                LDSM4(af[mt][0], af[mt][1], af[mt][2], af[mt][3], ra);
            }
            const unsigned rb0 = bbase + ((warp_n * 32) * GSTW + kk * 8) * 4 + boffB;
            const unsigned rb1 = rb0 + 16 * GSTW * 4;
            LDSM4(bf[0][0], bf[0][1], bf[1][0], bf[1][1], rb0);
            LDSM4(bf[2][0], bf[2][1], bf[3][0], bf[3][1], rb1);
            #pragma unroll
            for (int mt = 0; mt < 4; mt++)
                #pragma unroll
                for (int nt = 0; nt < 4; nt++)
                    mma_f16(acc[mt][nt], af[mt], bf[nt]);
        }
        __syncthreads();
        buf = (buf == 2) ? 0 : buf + 1;
    }

    #pragma unroll
    for (int mt = 0; mt < 4; mt++) {
        const int r0 = m0 + warp_m * 64 + mt * 16 + g;
        #pragma unroll
        for (int nt = 0; nt < 4; nt++) {
            const int col = n0 + warp_n * 32 + nt * 8 + 2 * tig;
            const float bx = bias[col] * bscale, by = bias[col + 1] * bscale;
            if (OUTF) {
                float* C = (float*)Cv;
                float2 v0 = { acc[mt][nt][0] + bx, acc[mt][nt][1] + by };
                float2 v1 = { acc[mt][nt][2] + bx, acc[mt][nt][3] + by };
                *(float2*)&C[(size_t)r0 * DM + col] = v0;
                *(float2*)&C[(size_t)(r0 + 8) * DM + col] = v1;
            } else {
                __half* C = (__half*)Cv;
                *(unsigned*)&C[(size_t)r0 * DM + col] =
                    pack_h2(acc[mt][nt][0] + bx, acc[mt][nt][1] + by);
                *(unsigned*)&C[(size_t)(r0 + 8) * DM + col] =
                    pack_h2(acc[mt][nt][2] + bx, acc[mt][nt][3] + by);
            }
        }
    }
}

// fused QKV: blockIdx.z selects {Q, K, V}
__global__ __launch_bounds__(256, 2) void tc_gemm_qkv(
    const __half* __restrict__ A,
    const __half* __restrict__ W0, const __half* __restrict__ W1,
    const __half* __restrict__ W2,
    const float* __restrict__ b0, const float* __restrict__ b1,
    const float* __restrict__ b2,
    __half* __restrict__ C0, __half* __restrict__ C1, __half* __restrict__ C2)
{
    extern __shared__ __align__(16) unsigned smemw[];
    const int z = blockIdx.z;
    const __half* Wt = (z == 0) ? W0 : (z == 1) ? W1 : W2;
    const float* bias = (z == 0) ? b0 : (z == 1) ? b1 : b2;
    __half* C = (z == 0) ? C0 : (z == 1) ? C1 : C2;
    const float bscale = (z == 0) ? 0.125f : 1.f;
    gemm_body<0>(A, Wt, bias, C, bscale, smemw, blockIdx.y * BM, blockIdx.x * BN);
}

__global__ __launch_bounds__(256, 2) void tc_gemm_out(
    const __half* __restrict__ A, const __half* __restrict__ Wt,
    const float* __restrict__ bias, float* __restrict__ C)
{
    extern __shared__ __align__(16) unsigned smemw[];
    gemm_body<1>(A, Wt, bias, C, 1.f, smemw, blockIdx.y * BM, blockIdx.x * BN);
}

// ===========================================================================
// Flash attention, fp16, double-buffered K/V pipeline + ldmatrix fragments.
// Row stride 36 words: 8 consecutive rows cover all 32 banks -> conflict-free.
// ===========================================================================
#define HST 72   // half stride per row
#define HSW 36   // word stride per row
#define KVBUF (64 * HST)   // halfs per buffer

__global__ __launch_bounds__(256) void flash_h(
    const __half* __restrict__ Q, const __half* __restrict__ K,
    const __half* __restrict__ V, __half* __restrict__ Z)
{
    __shared__ __align__(16) __half ks[2 * KVBUF];
    __shared__ __align__(16) __half vs[2 * KVBUF];
    const unsigned ksb = smem_u32(ks);
    const unsigned vsb = smem_u32(vs);

    const int tid = threadIdx.x;
    const int wid = tid >> 5, lane = tid & 31;
    const int g = lane >> 2, tig = lane & 3;
    const int lrow = lane & 7, quad = lane >> 3;
    const int qt = gridDim.x - 1 - blockIdx.x;       // heavy tiles first
    const int bh = blockIdx.y;
    const int b = bh >> 4, h = bh & 15;
    const size_t base = ((size_t)b * SEQ * NH + h) * DH;
    const int qrow0 = qt * 128 + wid * 16;

    const int srow = tid >> 2;          // staging row 0..63
    const int sc16 = (tid & 3) * 16;    // half offset within 64-half row
    const unsigned sdst = ksb + srow * 144 + (tid & 3) * 32;

    // per-lane ldmatrix byte offset (B-operand pattern) for K/V fragments
    const unsigned kvoffB = ((lrow + 8 * (quad >> 1)) * HSW + 4 * (quad & 1)) * 4;

    // ---- Q -> register A-fragments (pre-scaled fp16; 2 cp.async passes) ----
    unsigned aq[4][4];
    #pragma unroll
    for (int pass = 0; pass < 2; pass++) {
        const __half* qp = Q + base + (size_t)(qt * 128 + pass * 64 + srow) * DM + sc16;
        cp16(sdst, qp); cp16(sdst + 16, qp + 8);
        CP_COMMIT(); CP_WAIT(0);
        __syncthreads();
        if ((wid >> 2) == pass) {
            // A-operand ldmatrix offsets: rows r..r+15, k 0..15
            const unsigned aoffB = ((lrow + 8 * (quad & 1)) * HSW + 4 * (quad >> 1)) * 4;
            const int r = (wid & 3) * 16;
            #pragma unroll
            for (int kk = 0; kk < 4; kk++) {
                const unsigned ra = ksb + (r * HSW + kk * 8) * 4 + aoffB;
                LDSM4(aq[kk][0], aq[kk][1], aq[kk][2], aq[kk][3], ra);
            }
        }
        __syncthreads();
    }

    float m0 = -1e30f, m1 = -1e30f, l0 = 0.f, l1 = 0.f;
    float oacc[8][4];
    #pragma unroll
    for (int nt = 0; nt < 8; nt++)
        #pragma unroll
        for (int i = 0; i < 4; i++) oacc[nt][i] = 0.f;

    const int vkv = tid & 63;          // V staging row
    const int vd0 = (tid >> 6) * 16;   // V staging d group
    const int NKT = 2 * qt + 2;

    // prologue: tile 0 into buf 0
    {
        const __half* kp = K + base + (size_t)srow * DM + sc16;
        cp16(sdst, kp); cp16(sdst + 16, kp + 8);
        CP_COMMIT();
        uint4 v0 = *(const uint4*)&V[base + (size_t)vkv * DM + vd0];
        uint4 v1 = *(const uint4*)&V[base + (size_t)vkv * DM + vd0 + 8];
        const __half* hp0 = (const __half*)&v0;
        const __half* hp1 = (const __half*)&v1;
        #pragma unroll
        for (int j = 0; j < 8; j++) {
            vs[(vd0 + j) * HST + vkv] = hp0[j];
            vs[(vd0 + 8 + j) * HST + vkv] = hp1[j];
        }
        CP_WAIT(0);
        __syncthreads();
    }

    for (int kt = 0; kt < NKT; kt++) {
        const int ktb = kt * 64;
        const int buf = kt & 1, nbuf = buf ^ 1;
        uint4 pv0, pv1;
        const bool pre = (kt + 1 < NKT);
        if (pre) {
            const __half* kp = K + base + (size_t)(ktb + 64 + srow) * DM + sc16;
            const unsigned kd = sdst + nbuf * (KVBUF * 2);
            cp16(kd, kp); cp16(kd + 16, kp + 8);
            CP_COMMIT();
            pv0 = *(const uint4*)&V[base + (size_t)(ktb + 64 + vkv) * DM + vd0];
            pv1 = *(const uint4*)&V[base + (size_t)(ktb + 64 + vkv) * DM + vd0 + 8];
        }

        if (ktb <= qrow0 + 15) {
            const unsigned kbase = ksb + buf * (KVBUF * 2) + kvoffB;
            const unsigned vbase = vsb + buf * (KVBUF * 2) + kvoffB;

            // ---- S = Q K^T ----
            float sacc[8][4];
            #pragma unroll
            for (int nt = 0; nt < 8; nt++)
                #pragma unroll
                for (int i = 0; i < 4; i++) sacc[nt][i] = 0.f;

            #pragma unroll
            for (int kk = 0; kk < 4; kk++) {
                unsigned bf[8][2];
                #pragma unroll
                for (int j = 0; j < 4; j++) {
                    const unsigned rk = kbase + (j * 16 * HSW + kk * 8) * 4;
                    LDSM4(bf[2*j][0], bf[2*j][1], bf[2*j+1][0], bf[2*j+1][1], rk);
                }
                #pragma unroll
                for (int nt = 0; nt < 8; nt++)
                    mma_f16(sacc[nt], aq[kk], bf[nt]);
            }

            // ---- causal mask (diagonal tiles only) ----
            if (ktb + 63 > qrow0) {
                #pragma unroll
                for (int nt = 0; nt < 8; nt++) {
                    const int kv0 = ktb + nt * 8 + 2 * tig;
                    if (kv0     > qrow0 + g)     sacc[nt][0] = -1e30f;
                    if (kv0 + 1 > qrow0 + g)     sacc[nt][1] = -1e30f;
                    if (kv0     > qrow0 + g + 8) sacc[nt][2] = -1e30f;
                    if (kv0 + 1 > qrow0 + g + 8) sacc[nt][3] = -1e30f;
                }
            }

            // ---- online softmax ----
            float rm0 = -1e30f, rm1 = -1e30f;
            #pragma unroll
            for (int nt = 0; nt < 8; nt++) {
                rm0 = fmaxf(rm0, fmaxf(sacc[nt][0], sacc[nt][1]));
                rm1 = fmaxf(rm1, fmaxf(sacc[nt][2], sacc[nt][3]));
            }
            rm0 = fmaxf(rm0, __shfl_xor_sync(0xffffffffu, rm0, 1));
            rm0 = fmaxf(rm0, __shfl_xor_sync(0xffffffffu, rm0, 2));
            rm1 = fmaxf(rm1, __shfl_xor_sync(0xffffffffu, rm1, 1));
            rm1 = fmaxf(rm1, __shfl_xor_sync(0xffffffffu, rm1, 2));
            const float mn0 = fmaxf(m0, rm0), mn1 = fmaxf(m1, rm1);
            const float al0 = __expf(m0 - mn0), al1 = __expf(m1 - mn1);
            float rs0 = 0.f, rs1 = 0.f;
            #pragma unroll
            for (int nt = 0; nt < 8; nt++) {
                sacc[nt][0] = __expf(sacc[nt][0] - mn0); rs0 += sacc[nt][0];
                sacc[nt][1] = __expf(sacc[nt][1] - mn0); rs0 += sacc[nt][1];
                sacc[nt][2] = __expf(sacc[nt][2] - mn1); rs1 += sacc[nt][2];
                sacc[nt][3] = __expf(sacc[nt][3] - mn1); rs1 += sacc[nt][3];
            }
            rs0 += __shfl_xor_sync(0xffffffffu, rs0, 1);
            rs0 += __shfl_xor_sync(0xffffffffu, rs0, 2);
            rs1 += __shfl_xor_sync(0xffffffffu, rs1, 1);
            rs1 += __shfl_xor_sync(0xffffffffu, rs1, 2);
            l0 = l0 * al0 + rs0;  l1 = l1 * al1 + rs1;
            m0 = mn0;             m1 = mn1;
            #pragma unroll
            for (int nt = 0; nt < 8; nt++) {
                oacc[nt][0] *= al0; oacc[nt][1] *= al0;
                oacc[nt][2] *= al1; oacc[nt][3] *= al1;
            }

            // ---- O += P V : S C-fragment IS the A-fragment ----
            #pragma unroll
            for (int kk = 0; kk < 4; kk++) {
                unsigned ap[4];
                ap[0] = pack_h2(sacc[2*kk][0],   sacc[2*kk][1]);
                ap[1] = pack_h2(sacc[2*kk][2],   sacc[2*kk][3]);
                ap[2] = pack_h2(sacc[2*kk+1][0], sacc[2*kk+1][1]);
                ap[3] = pack_h2(sacc[2*kk+1][2], sacc[2*kk+1][3]);
                unsigned bf[8][2];
                #pragma unroll
                for (int j = 0; j < 4; j++) {
                    const unsigned rv = vbase + (j * 16 * HSW + kk * 8) * 4;
                    LDSM4(bf[2*j][0], bf[2*j][1], bf[2*j+1][0], bf[2*j+1][1], rv);
                }
                #pragma unroll
                for (int nt = 0; nt < 8; nt++)
                    mma_f16(oacc[nt], ap, bf[nt]);
            }
        }

        if (pre) {
            __half* vb = vs + nbuf * KVBUF;
            const __half* hp0 = (const __half*)&pv0;
            const __half* hp1 = (const __half*)&pv1;
            #pragma unroll
            for (int j = 0; j < 8; j++) {
                vb[(vd0 + j) * HST + vkv] = hp0[j];
                vb[(vd0 + 8 + j) * HST + vkv] = hp1[j];
            }
            CP_WAIT(0);
        }
        __syncthreads();
    }

    // ---- normalize + write z (fp16) ----
    const float i0 = 1.f / l0, i1 = 1.f / l1;
    #pragma unroll
    for (int nt = 0; nt < 8; nt++) {
        const int col = nt * 8 + 2 * tig;
        const int row = qrow0 + g;
        *(unsigned*)&Z[base + (size_t)row * DM + col] =
            pack_h2(oacc[nt][0] * i0, oacc[nt][1] * i0);
        *(unsigned*)&Z[base + (size_t)(row + 8) * DM + col] =
            pack_h2(oacc[nt][2] * i1, oacc[nt][3] * i1);
    }
}

// ---------------------------------------------------------------------------

extern "C" void kernel_launch(void* const* d_in, const int* in_sizes, int n_in,
                              void* d_out, int out_size)
{
    const float* x  = (const float*)d_in[0];
    const float* WQ = (const float*)d_in[1];
    const float* WK = (const float*)d_in[2];
    const float* WV = (const float*)d_in[3];
    const float* WO = (const float*)d_in[4];
    const float* bQ = (const float*)d_in[5];
    const float* bK = (const float*)d_in[6];
    const float* bV = (const float*)d_in[7];
    const float* bO = (const float*)d_in[8];
    float* out = (float*)d_out;

    __half *xh, *qh, *kh, *vh, *zh, *wqt, *wkt, *wvt, *wot;
    cudaGetSymbolAddress((void**)&xh,  h_x);
    cudaGetSymbolAddress((void**)&qh,  h_q);
    cudaGetSymbolAddress((void**)&kh,  h_k);
    cudaGetSymbolAddress((void**)&vh,  h_v);
    cudaGetSymbolAddress((void**)&zh,  h_z);
    cudaGetSymbolAddress((void**)&wqt, h_wq);
    cudaGetSymbolAddress((void**)&wkt, h_wk);
    cudaGetSymbolAddress((void**)&wvt, h_wv);
    cudaGetSymbolAddress((void**)&wot, h_wo);

    cudaFuncSetAttribute(tc_gemm_qkv, cudaFuncAttributeMaxDynamicSharedMemorySize, GEMM_SMEM);
    cudaFuncSetAttribute(tc_gemm_out, cudaFuncAttributeMaxDynamicSharedMemorySize, GEMM_SMEM);

    // prep: convert x (MLP=4); fused QKV weight transpose; WO transpose
    convx_kernel<<<(MTOT * DM) / 4096, 256>>>(x, xh);
    tconv_qkv_kernel<<<dim3(32, 2, 48), dim3(32, 8)>>>(WQ, WK, WV, wqt, wkt, wvt);
    tconv_kernel<<<dim3(32, 32, 1), dim3(32, 8)>>>(WO, wot, DM, DM);

    tc_gemm_qkv<<<dim3(DM / BN, MTOT / BM, 3), 256, GEMM_SMEM>>>(
        xh, wqt, wkt, wvt, bQ, bK, bV, qh, kh, vh);
    flash_h<<<dim3(SEQ / 128, BATCH * NH), 256>>>(qh, kh, vh, zh);
    tc_gemm_out<<<dim3(DM / BN, MTOT / BM), 256, GEMM_SMEM>>>(zh, wot, bO, out);
}

// round 15
// speedup vs baseline: 1.1963x; 1.0693x over previous
#include <cuda_runtime.h>
#include <cuda_fp16.h>
#include <cstdint>

#define SEQ   2048
#define BATCH 2
#define NH    16
#define DH    64
#define DM    1024
#define MTOT  (BATCH*SEQ)   // 4096 rows

// fp16 scratch (device globals: no allocation allowed in kernel_launch)
__device__ __half h_x [(size_t)MTOT * DM];
__device__ __half h_q [(size_t)MTOT * DM];
__device__ __half h_k [(size_t)MTOT * DM];
__device__ __half h_v [(size_t)MTOT * DM];
__device__ __half h_z [(size_t)MTOT * DM];
__device__ __half h_wq[(size_t)DM * DM];
__device__ __half h_wk[(size_t)DM * DM];
__device__ __half h_wv[(size_t)DM * DM];
__device__ __half h_wo[(size_t)DM * DM];

// ===========================================================================
// helpers
// ===========================================================================
__device__ __forceinline__ void mma_f16(float* d, const unsigned* a, const unsigned* b) {
    asm volatile("mma.sync.aligned.m16n8k16.row.col.f32.f16.f16.f32 "
        "{%0,%1,%2,%3}, {%4,%5,%6,%7}, {%8,%9}, {%0,%1,%2,%3};"
        : "+f"(d[0]), "+f"(d[1]), "+f"(d[2]), "+f"(d[3])
        : "r"(a[0]), "r"(a[1]), "r"(a[2]), "r"(a[3]), "r"(b[0]), "r"(b[1]));
}

#define LDSM4(r0, r1, r2, r3, addr) \
    asm volatile("ldmatrix.sync.aligned.m8n8.x4.shared.b16 {%0,%1,%2,%3}, [%4];" \
        : "=r"(r0), "=r"(r1), "=r"(r2), "=r"(r3) : "r"(addr))

#define LDSM4T(r0, r1, r2, r3, addr) \
    asm volatile("ldmatrix.sync.aligned.m8n8.x4.trans.shared.b16 {%0,%1,%2,%3}, [%4];" \
        : "=r"(r0), "=r"(r1), "=r"(r2), "=r"(r3) : "r"(addr))

__device__ __forceinline__ unsigned pack_h2(float lo, float hi) {
    unsigned r;
    asm("cvt.rn.f16x2.f32 %0, %1, %2;" : "=r"(r) : "f"(hi), "f"(lo));
    return r;
}

__device__ __forceinline__ unsigned smem_u32(const void* p) {
    unsigned r;
    asm("{ .reg .u64 t; cvta.to.shared.u64 t, %1; cvt.u32.u64 %0, t; }"
        : "=r"(r) : "l"(p));
    return r;
}

__device__ __forceinline__ void cp16(unsigned dst, const void* src) {
    asm volatile("cp.async.cg.shared.global [%0], [%1], 16;" :: "r"(dst), "l"(src));
}
#define CP_COMMIT()  asm volatile("cp.async.commit_group;" ::: "memory")
#define CP_WAIT(n)   asm volatile("cp.async.wait_group %0;" :: "n"(n) : "memory")

// ===========================================================================
// prep kernels (unchanged)
// ===========================================================================
__global__ __launch_bounds__(256) void convx_kernel(
    const float* __restrict__ X, __half* __restrict__ Y)
{
    const size_t i = ((size_t)blockIdx.x * 256 + threadIdx.x) * 16;
    float4 v0 = *(const float4*)&X[i];
    float4 v1 = *(const float4*)&X[i + 4];
    float4 v2 = *(const float4*)&X[i + 8];
    float4 v3 = *(const float4*)&X[i + 12];
    uint4 ua = { pack_h2(v0.x, v0.y), pack_h2(v0.z, v0.w),
                 pack_h2(v1.x, v1.y), pack_h2(v1.z, v1.w) };
    uint4 ub = { pack_h2(v2.x, v2.y), pack_h2(v2.z, v2.w),
                 pack_h2(v3.x, v3.y), pack_h2(v3.z, v3.w) };
    *(uint4*)&Y[i] = ua;
    *(uint4*)&Y[i + 8] = ub;
}

__global__ __launch_bounds__(256) void tconv_qkv_kernel(
    const float* __restrict__ WQ, const float* __restrict__ WK,
    const float* __restrict__ WV,
    __half* __restrict__ YQ, __half* __restrict__ YK, __half* __restrict__ YV)
{
    __shared__ float t[32][33];
    const int mat = blockIdx.z >> 4, head = blockIdx.z & 15;
    const float* Xb = ((mat == 0) ? WQ : (mat == 1) ? WK : WV)
                      + (size_t)head * DM * DH;
    __half* Yb = ((mat == 0) ? YQ : (mat == 1) ? YK : YV)
                 + (size_t)head * DH * DM;
    const float scale = (mat == 0) ? 0.125f : 1.f;
    const int r0 = blockIdx.x * 32, c0 = blockIdx.y * 32;
    const int tx = threadIdx.x, ty = threadIdx.y;
    #pragma unroll
    for (int i = ty; i < 32; i += 8)
        t[i][tx] = Xb[(size_t)(r0 + i) * DH + c0 + tx];
    __syncthreads();
    #pragma unroll
    for (int i = ty; i < 32; i += 8)
        Yb[(size_t)(c0 + i) * DM + r0 + tx] = __float2half_rn(t[tx][i] * scale);
}

__global__ __launch_bounds__(256) void tconv_kernel(
    const float* __restrict__ X, __half* __restrict__ Y, int R, int C)
{
    __shared__ float t[32][33];
    const int r0 = blockIdx.x * 32, c0 = blockIdx.y * 32;
    const int tx = threadIdx.x, ty = threadIdx.y;
    #pragma unroll
    for (int i = ty; i < 32; i += 8)
        t[i][tx] = X[(size_t)(r0 + i) * C + c0 + tx];
    __syncthreads();
    #pragma unroll
    for (int i = ty; i < 32; i += 8)
        Y[(size_t)(c0 + i) * R + r0 + tx] = __float2half_rn(t[tx][i]);
}

// ===========================================================================
// fp16 tensor GEMM: KCH=32, 3-stage cp.async + ldmatrix (R14 proven).
// ===========================================================================
#define BM 128
#define BN 128
#define KCH 32
#define NCHUNK (DM / KCH)  // 32
#define GSTW 20
#define TOFFW 2560
#define GEMM_SMEM 61440

template<int OUTF>
__device__ __forceinline__ void gemm_body(
    const __half* __restrict__ A, const __half* __restrict__ Wt,
    const float* __restrict__ bias, void* __restrict__ Cv, float bscale,
    unsigned* smemw, int m0, int n0)
{
    const unsigned sbase = smem_u32(smemw);
    const int tid = threadIdx.x;
    const int wid = tid >> 5, lane = tid & 31;
    const int g = lane >> 2, tig = lane & 3;
    const int warp_m = wid & 1, warp_n = wid >> 1;
    const int lrow = lane & 7, quad = lane >> 3;

    const int row = tid >> 1;
    const int hc  = (tid & 1) * 16;
    const __half* Aptr = A  + (size_t)(m0 + row) * DM + hc;
    const __half* Bptr = Wt + (size_t)(n0 + row) * DM + hc;
    const unsigned aDst = sbase + (row * GSTW + (tid & 1) * 8) * 4;
    const unsigned bDst = aDst + 3 * TOFFW * 4;

    const unsigned aoffB = ((lrow + 8 * (quad & 1)) * GSTW + 4 * (quad >> 1)) * 4;
    const unsigned boffB = ((lrow + 8 * (quad >> 1)) * GSTW + 4 * (quad & 1)) * 4;

    float acc[4][4][4];
    #pragma unroll
    for (int mt = 0; mt < 4; mt++)
        #pragma unroll
        for (int nt = 0; nt < 4; nt++)
            #pragma unroll
            for (int i = 0; i < 4; i++) acc[mt][nt][i] = 0.f;

    auto stage = [&](int c, int buf) {
        const __half* ap = Aptr + c * KCH;
        const __half* bp = Bptr + c * KCH;
        const unsigned ad = aDst + buf * (TOFFW * 4);
        const unsigned bd = bDst + buf * (TOFFW * 4);
        cp16(ad, ap); cp16(ad + 16, ap + 8);
        cp16(bd, bp); cp16(bd + 16, bp + 8);
    };

    stage(0, 0); CP_COMMIT();
    stage(1, 1); CP_COMMIT();

    int buf = 0;
    for (int c = 0; c < NCHUNK; c++) {
        if (c + 2 < NCHUNK) { stage(c + 2, (c + 2) % 3); CP_COMMIT(); CP_WAIT(2); }
        else if (c + 1 < NCHUNK) { CP_WAIT(1); }
        else { CP_WAIT(0); }
        __syncthreads();

        const unsigned abase = sbase + buf * (TOFFW * 4);
        const unsigned bbase = abase + 3 * TOFFW * 4;
        #pragma unroll
        for (int kk = 0; kk < 2; kk++) {
            unsigned af[4][4], bf[4][2];
            #pragma unroll
            for (int mt = 0; mt < 4; mt++) {
                const unsigned ra = abase +
                    ((warp_m * 64 + mt * 16) * GSTW + kk * 8) * 4 + aoffB;
                LDSM4(af[mt][0], af[mt][1], af[mt][2], af[mt][3], ra);
            }
            const unsigned rb0 = bbase + ((warp_n * 32) * GSTW + kk * 8) * 4 + boffB;
            const unsigned rb1 = rb0 + 16 * GSTW * 4;
            LDSM4(bf[0][0], bf[0][1], bf[1][0], bf[1][1], rb0);
            LDSM4(bf[2][0], bf[2][1], bf[3][0], bf[3][1], rb1);
            #pragma unroll
            for (int mt = 0; mt < 4; mt++)
                #pragma unroll
                for (int nt = 0; nt < 4; nt++)
                    mma_f16(acc[mt][nt], af[mt], bf[nt]);
        }
        __syncthreads();
        buf = (buf == 2) ? 0 : buf + 1;
    }

    #pragma unroll
    for (int mt = 0; mt < 4; mt++) {
        const int r0 = m0 + warp_m * 64 + mt * 16 + g;
        #pragma unroll
        for (int nt = 0; nt < 4; nt++) {
            const int col = n0 + warp_n * 32 + nt * 8 + 2 * tig;
            const float bx = bias[col] * bscale, by = bias[col + 1] * bscale;
            if (OUTF) {
                float* C = (float*)Cv;
                float2 v0 = { acc[mt][nt][0] + bx, acc[mt][nt][1] + by };
                float2 v1 = { acc[mt][nt][2] + bx, acc[mt][nt][3] + by };
                *(float2*)&C[(size_t)r0 * DM + col] = v0;
                *(float2*)&C[(size_t)(r0 + 8) * DM + col] = v1;
            } else {
                __half* C = (__half*)Cv;
                *(unsigned*)&C[(size_t)r0 * DM + col] =
                    pack_h2(acc[mt][nt][0] + bx, acc[mt][nt][1] + by);
                *(unsigned*)&C[(size_t)(r0 + 8) * DM + col] =
                    pack_h2(acc[mt][nt][2] + bx, acc[mt][nt][3] + by);
            }
        }
    }
}

__global__ __launch_bounds__(256, 2) void tc_gemm_qkv(
    const __half* __restrict__ A,
    const __half* __restrict__ W0, const __half* __restrict__ W1,
    const __half* __restrict__ W2,
    const float* __restrict__ b0, const float* __restrict__ b1,
    const float* __restrict__ b2,
    __half* __restrict__ C0, __half* __restrict__ C1, __half* __restrict__ C2)
{
    extern __shared__ __align__(16) unsigned smemw[];
    const int z = blockIdx.z;
    const __half* Wt = (z == 0) ? W0 : (z == 1) ? W1 : W2;
    const float* bias = (z == 0) ? b0 : (z == 1) ? b1 : b2;
    __half* C = (z == 0) ? C0 : (z == 1) ? C1 : C2;
    const float bscale = (z == 0) ? 0.125f : 1.f;
    gemm_body<0>(A, Wt, bias, C, bscale, smemw, blockIdx.y * BM, blockIdx.x * BN);
}

__global__ __launch_bounds__(256, 2) void tc_gemm_out(
    const __half* __restrict__ A, const __half* __restrict__ Wt,
    const float* __restrict__ bias, float* __restrict__ C)
{
    extern __shared__ __align__(16) unsigned smemw[];
    gemm_body<1>(A, Wt, bias, C, 1.f, smemw, blockIdx.y * BM, blockIdx.x * BN);
}

// ===========================================================================
// Flash attention, fp16, double-buffered K/V cp.async pipeline.
// BOTH K and V stored naturally [kv][d], stride 72 halfs. K fragments via
// ldmatrix.x4; V^T fragments via ldmatrix.x4.trans (no transpose STS).
// ===========================================================================
#define HST 72   // half stride per row
#define HSW 36   // word stride per row
#define KVBUF (64 * HST)   // halfs per buffer

__global__ __launch_bounds__(256) void flash_h(
    const __half* __restrict__ Q, const __half* __restrict__ K,
    const __half* __restrict__ V, __half* __restrict__ Z)
{
    __shared__ __align__(16) __half ks[2 * KVBUF];
    __shared__ __align__(16) __half vs[2 * KVBUF];
    const unsigned ksb = smem_u32(ks);
    const unsigned vsb = smem_u32(vs);

    const int tid = threadIdx.x;
    const int wid = tid >> 5, lane = tid & 31;
    const int g = lane >> 2, tig = lane & 3;
    const int lrow = lane & 7, quad = lane >> 3;
    const int qt = gridDim.x - 1 - blockIdx.x;       // heavy tiles first
    const int bh = blockIdx.y;
    const int b = bh >> 4, h = bh & 15;
    const size_t base = ((size_t)b * SEQ * NH + h) * DH;
    const int qrow0 = qt * 128 + wid * 16;

    const int srow = tid >> 2;          // staging row 0..63
    const int sc16 = (tid & 3) * 16;    // half offset within 64-half row
    const unsigned kdst = ksb + srow * 144 + (tid & 3) * 32;
    const unsigned vdst = vsb + srow * 144 + (tid & 3) * 32;

    // K fragments (B-operand, K^T): same pattern as R14
    const unsigned kvoffB = ((lrow + 8 * (quad >> 1)) * HSW + 4 * (quad & 1)) * 4;
    // V fragments (B-operand via trans): row = kv0 + (lane&15), colword 4*(lane>>4)
    const unsigned voffT = ((lane & 15) * HSW + 4 * (lane >> 4)) * 4;

    // ---- Q -> register A-fragments (pre-scaled fp16; 2 cp.async passes) ----
    unsigned aq[4][4];
    #pragma unroll
    for (int pass = 0; pass < 2; pass++) {
        const __half* qp = Q + base + (size_t)(qt * 128 + pass * 64 + srow) * DM + sc16;
        cp16(kdst, qp); cp16(kdst + 16, qp + 8);
        CP_COMMIT(); CP_WAIT(0);
        __syncthreads();
        if ((wid >> 2) == pass) {
            const unsigned aoffB = ((lrow + 8 * (quad & 1)) * HSW + 4 * (quad >> 1)) * 4;
            const int r = (wid & 3) * 16;
            #pragma unroll
            for (int kk = 0; kk < 4; kk++) {
                const unsigned ra = ksb + (r * HSW + kk * 8) * 4 + aoffB;
                LDSM4(aq[kk][0], aq[kk][1], aq[kk][2], aq[kk][3], ra);
            }
        }
        __syncthreads();
    }

    float m0 = -1e30f, m1 = -1e30f, l0 = 0.f, l1 = 0.f;
    float oacc[8][4];
    #pragma unroll
    for (int nt = 0; nt < 8; nt++)
        #pragma unroll
        for (int i = 0; i < 4; i++) oacc[nt][i] = 0.f;

    const int NKT = 2 * qt + 2;

    auto stage_kv = [&](int kt, int buf) {
        const size_t roff = base + (size_t)(kt * 64 + srow) * DM + sc16;
        const unsigned kd = kdst + buf * (KVBUF * 2);
        const unsigned vd = vdst + buf * (KVBUF * 2);
        cp16(kd, K + roff); cp16(kd + 16, K + roff + 8);
        cp16(vd, V + roff); cp16(vd + 16, V + roff + 8);
    };

    // prologue: tile 0 into buf 0
    stage_kv(0, 0); CP_COMMIT(); CP_WAIT(0);
    __syncthreads();

    for (int kt = 0; kt < NKT; kt++) {
        const int ktb = kt * 64;
        const int buf = kt & 1;
        const bool pre = (kt + 1 < NKT);
        if (pre) { stage_kv(kt + 1, buf ^ 1); CP_COMMIT(); }

        if (ktb <= qrow0 + 15) {
            const unsigned kbase = ksb + buf * (KVBUF * 2) + kvoffB;
            const unsigned vbase = vsb + buf * (KVBUF * 2) + voffT;

            // ---- S = Q K^T ----
            float sacc[8][4];
            #pragma unroll
            for (int nt = 0; nt < 8; nt++)
                #pragma unroll
                for (int i = 0; i < 4; i++) sacc[nt][i] = 0.f;

            #pragma unroll
            for (int kk = 0; kk < 4; kk++) {
                unsigned bf[8][2];
                #pragma unroll
                for (int j = 0; j < 4; j++) {
                    const unsigned rk = kbase + (j * 16 * HSW + kk * 8) * 4;
                    LDSM4(bf[2*j][0], bf[2*j][1], bf[2*j+1][0], bf[2*j+1][1], rk);
                }
                #pragma unroll
                for (int nt = 0; nt < 8; nt++)
                    mma_f16(sacc[nt], aq[kk], bf[nt]);
            }

            // ---- causal mask (diagonal tiles only) ----
            if (ktb + 63 > qrow0) {
                #pragma unroll
                for (int nt = 0; nt < 8; nt++) {
                    const int kv0 = ktb + nt * 8 + 2 * tig;
                    if (kv0     > qrow0 + g)     sacc[nt][0] = -1e30f;
                    if (kv0 + 1 > qrow0 + g)     sacc[nt][1] = -1e30f;
                    if (kv0     > qrow0 + g + 8) sacc[nt][2] = -1e30f;
                    if (kv0 + 1 > qrow0 + g + 8) sacc[nt][3] = -1e30f;
                }
            }

            // ---- online softmax ----
            float rm0 = -1e30f, rm1 = -1e30f;
            #pragma unroll
            for (int nt = 0; nt < 8; nt++) {
                rm0 = fmaxf(rm0, fmaxf(sacc[nt][0], sacc[nt][1]));
                rm1 = fmaxf(rm1, fmaxf(sacc[nt][2], sacc[nt][3]));
            }
            rm0 = fmaxf(rm0, __shfl_xor_sync(0xffffffffu, rm0, 1));
            rm0 = fmaxf(rm0, __shfl_xor_sync(0xffffffffu, rm0, 2));
            rm1 = fmaxf(rm1, __shfl_xor_sync(0xffffffffu, rm1, 1));
            rm1 = fmaxf(rm1, __shfl_xor_sync(0xffffffffu, rm1, 2));
            const float mn0 = fmaxf(m0, rm0), mn1 = fmaxf(m1, rm1);
            const float al0 = __expf(m0 - mn0), al1 = __expf(m1 - mn1);
            float rs0 = 0.f, rs1 = 0.f;
            #pragma unroll
            for (int nt = 0; nt < 8; nt++) {
                sacc[nt][0] = __expf(sacc[nt][0] - mn0); rs0 += sacc[nt][0];
                sacc[nt][1] = __expf(sacc[nt][1] - mn0); rs0 += sacc[nt][1];
                sacc[nt][2] = __expf(sacc[nt][2] - mn1); rs1 += sacc[nt][2];
                sacc[nt][3] = __expf(sacc[nt][3] - mn1); rs1 += sacc[nt][3];
            }
            rs0 += __shfl_xor_sync(0xffffffffu, rs0, 1);
            rs0 += __shfl_xor_sync(0xffffffffu, rs0, 2);
            rs1 += __shfl_xor_sync(0xffffffffu, rs1, 1);
            rs1 += __shfl_xor_sync(0xffffffffu, rs1, 2);
            l0 = l0 * al0 + rs0;  l1 = l1 * al1 + rs1;
            m0 = mn0;             m1 = mn1;
            #pragma unroll
            for (int nt = 0; nt < 8; nt++) {
                oacc[nt][0] *= al0; oacc[nt][1] *= al0;
                oacc[nt][2] *= al1; oacc[nt][3] *= al1;
            }

            // ---- O += P V : P from S regs; V^T frags via ldmatrix.trans ----
            #pragma unroll
            for (int kk = 0; kk < 4; kk++) {
                unsigned ap[4];
                ap[0] = pack_h2(sacc[2*kk][0],   sacc[2*kk][1]);
                ap[1] = pack_h2(sacc[2*kk][2],   sacc[2*kk][3]);
                ap[2] = pack_h2(sacc[2*kk+1][0], sacc[2*kk+1][1]);
                ap[3] = pack_h2(sacc[2*kk+1][2], sacc[2*kk+1][3]);
                unsigned bf[8][2];
                #pragma unroll
                for (int j = 0; j < 4; j++) {
                    const unsigned rv = vbase + (kk * 16 * HSW + j * 8) * 4;
                    LDSM4T(bf[2*j][0], bf[2*j][1], bf[2*j+1][0], bf[2*j+1][1], rv);
                }
                #pragma unroll
                for (int nt = 0; nt < 8; nt++)
                    mma_f16(oacc[nt], ap, bf[nt]);
            }
        }

        if (pre) CP_WAIT(0);
        __syncthreads();
    }

    // ---- normalize + write z (fp16) ----
    const float i0 = 1.f / l0, i1 = 1.f / l1;
    #pragma unroll
    for (int nt = 0; nt < 8; nt++) {
        const int col = nt * 8 + 2 * tig;
        const int row = qrow0 + g;
        *(unsigned*)&Z[base + (size_t)row * DM + col] =
            pack_h2(oacc[nt][0] * i0, oacc[nt][1] * i0);
        *(unsigned*)&Z[base + (size_t)(row + 8) * DM + col] =
            pack_h2(oacc[nt][2] * i1, oacc[nt][3] * i1);
    }
}

// ---------------------------------------------------------------------------

extern "C" void kernel_launch(void* const* d_in, const int* in_sizes, int n_in,
                              void* d_out, int out_size)
{
    const float* x  = (const float*)d_in[0];
    const float* WQ = (const float*)d_in[1];
    const float* WK = (const float*)d_in[2];
    const float* WV = (const float*)d_in[3];
    const float* WO = (const float*)d_in[4];
    const float* bQ = (const float*)d_in[5];
    const float* bK = (const float*)d_in[6];
    const float* bV = (const float*)d_in[7];
    const float* bO = (const float*)d_in[8];
    float* out = (float*)d_out;

    __half *xh, *qh, *kh, *vh, *zh, *wqt, *wkt, *wvt, *wot;
    cudaGetSymbolAddress((void**)&xh,  h_x);
    cudaGetSymbolAddress((void**)&qh,  h_q);
    cudaGetSymbolAddress((void**)&kh,  h_k);
    cudaGetSymbolAddress((void**)&vh,  h_v);
    cudaGetSymbolAddress((void**)&zh,  h_z);
    cudaGetSymbolAddress((void**)&wqt, h_wq);
    cudaGetSymbolAddress((void**)&wkt, h_wk);
    cudaGetSymbolAddress((void**)&wvt, h_wv);
    cudaGetSymbolAddress((void**)&wot, h_wo);

    cudaFuncSetAttribute(tc_gemm_qkv, cudaFuncAttributeMaxDynamicSharedMemorySize, GEMM_SMEM);
    cudaFuncSetAttribute(tc_gemm_out, cudaFuncAttributeMaxDynamicSharedMemorySize, GEMM_SMEM);

    convx_kernel<<<(MTOT * DM) / 4096, 256>>>(x, xh);
    tconv_qkv_kernel<<<dim3(32, 2, 48), dim3(32, 8)>>>(WQ, WK, WV, wqt, wkt, wvt);
    tconv_kernel<<<dim3(32, 32, 1), dim3(32, 8)>>>(WO, wot, DM, DM);

    tc_gemm_qkv<<<dim3(DM / BN, MTOT / BM, 3), 256, GEMM_SMEM>>>(
        xh, wqt, wkt, wvt, bQ, bK, bV, qh, kh, vh);
    flash_h<<<dim3(SEQ / 128, BATCH * NH), 256>>>(qh, kh, vh, zh);
    tc_gemm_out<<<dim3(DM / BN, MTOT / BM), 256, GEMM_SMEM>>>(zh, wot, bO, out);
}

// round 16
// speedup vs baseline: 1.2658x; 1.0580x over previous
#include <cuda_runtime.h>
#include <cuda_fp16.h>
#include <cstdint>

#define SEQ   2048
#define BATCH 2
#define NH    16
#define DH    64
#define DM    1024
#define MTOT  (BATCH*SEQ)   // 4096 rows

// fp16 scratch (device globals: no allocation allowed in kernel_launch)
__device__ __half h_x [(size_t)MTOT * DM];
__device__ __half h_q [(size_t)MTOT * DM];
__device__ __half h_k [(size_t)MTOT * DM];
__device__ __half h_v [(size_t)MTOT * DM];
__device__ __half h_z [(size_t)MTOT * DM];
__device__ __half h_wq[(size_t)DM * DM];
__device__ __half h_wk[(size_t)DM * DM];
__device__ __half h_wv[(size_t)DM * DM];
__device__ __half h_wo[(size_t)DM * DM];

// ===========================================================================
// helpers
// ===========================================================================
__device__ __forceinline__ void mma_f16(float* d, const unsigned* a, const unsigned* b) {
    asm volatile("mma.sync.aligned.m16n8k16.row.col.f32.f16.f16.f32 "
        "{%0,%1,%2,%3}, {%4,%5,%6,%7}, {%8,%9}, {%0,%1,%2,%3};"
        : "+f"(d[0]), "+f"(d[1]), "+f"(d[2]), "+f"(d[3])
        : "r"(a[0]), "r"(a[1]), "r"(a[2]), "r"(a[3]), "r"(b[0]), "r"(b[1]));
}

#define LDSM4(r0, r1, r2, r3, addr) \
    asm volatile("ldmatrix.sync.aligned.m8n8.x4.shared.b16 {%0,%1,%2,%3}, [%4];" \
        : "=r"(r0), "=r"(r1), "=r"(r2), "=r"(r3) : "r"(addr))

#define LDSM4T(r0, r1, r2, r3, addr) \
    asm volatile("ldmatrix.sync.aligned.m8n8.x4.trans.shared.b16 {%0,%1,%2,%3}, [%4];" \
        : "=r"(r0), "=r"(r1), "=r"(r2), "=r"(r3) : "r"(addr))

__device__ __forceinline__ unsigned pack_h2(float lo, float hi) {
    unsigned r;
    asm("cvt.rn.f16x2.f32 %0, %1, %2;" : "=r"(r) : "f"(hi), "f"(lo));
    return r;
}

__device__ __forceinline__ unsigned smem_u32(const void* p) {
    unsigned r;
    asm("{ .reg .u64 t; cvta.to.shared.u64 t, %1; cvt.u32.u64 %0, t; }"
        : "=r"(r) : "l"(p));
    return r;
}

__device__ __forceinline__ void cp16(unsigned dst, const void* src) {
    asm volatile("cp.async.cg.shared.global [%0], [%1], 16;" :: "r"(dst), "l"(src));
}
#define CP_COMMIT()  asm volatile("cp.async.commit_group;" ::: "memory")
#define CP_WAIT(n)   asm volatile("cp.async.wait_group %0;" :: "n"(n) : "memory")

// ===========================================================================
// prep kernels (unchanged)
// ===========================================================================
__global__ __launch_bounds__(256) void convx_kernel(
    const float* __restrict__ X, __half* __restrict__ Y)
{
    const size_t i = ((size_t)blockIdx.x * 256 + threadIdx.x) * 16;
    float4 v0 = *(const float4*)&X[i];
    float4 v1 = *(const float4*)&X[i + 4];
    float4 v2 = *(const float4*)&X[i + 8];
    float4 v3 = *(const float4*)&X[i + 12];
    uint4 ua = { pack_h2(v0.x, v0.y), pack_h2(v0.z, v0.w),
                 pack_h2(v1.x, v1.y), pack_h2(v1.z, v1.w) };
    uint4 ub = { pack_h2(v2.x, v2.y), pack_h2(v2.z, v2.w),
                 pack_h2(v3.x, v3.y), pack_h2(v3.z, v3.w) };
    *(uint4*)&Y[i] = ua;
    *(uint4*)&Y[i + 8] = ub;
}

__global__ __launch_bounds__(256) void tconv_qkv_kernel(
    const float* __restrict__ WQ, const float* __restrict__ WK,
    const float* __restrict__ WV,
    __half* __restrict__ YQ, __half* __restrict__ YK, __half* __restrict__ YV)
{
    __shared__ float t[32][33];
    const int mat = blockIdx.z >> 4, head = blockIdx.z & 15;
    const float* Xb = ((mat == 0) ? WQ : (mat == 1) ? WK : WV)
                      + (size_t)head * DM * DH;
    __half* Yb = ((mat == 0) ? YQ : (mat == 1) ? YK : YV)
                 + (size_t)head * DH * DM;
    const float scale = (mat == 0) ? 0.125f : 1.f;
    const int r0 = blockIdx.x * 32, c0 = blockIdx.y * 32;
    const int tx = threadIdx.x, ty = threadIdx.y;
    #pragma unroll
    for (int i = ty; i < 32; i += 8)
        t[i][tx] = Xb[(size_t)(r0 + i) * DH + c0 + tx];
    __syncthreads();
    #pragma unroll
    for (int i = ty; i < 32; i += 8)
        Yb[(size_t)(c0 + i) * DM + r0 + tx] = __float2half_rn(t[tx][i] * scale);
}

__global__ __launch_bounds__(256) void tconv_kernel(
    const float* __restrict__ X, __half* __restrict__ Y, int R, int C)
{
    __shared__ float t[32][33];
    const int r0 = blockIdx.x * 32, c0 = blockIdx.y * 32;
    const int tx = threadIdx.x, ty = threadIdx.y;
    #pragma unroll
    for (int i = ty; i < 32; i += 8)
        t[i][tx] = X[(size_t)(r0 + i) * C + c0 + tx];
    __syncthreads();
    #pragma unroll
    for (int i = ty; i < 32; i += 8)
        Y[(size_t)(c0 + i) * R + r0 + tx] = __float2half_rn(t[tx][i]);
}

// ===========================================================================
// fp16 tensor GEMM: KCH=32, 3-stage cp.async + ldmatrix + SINGLE sync/chunk.
// Loop: wait -> sync -> stage(c+2) -> compute(c). Safe: all warps finished
// compute(c-1) before this barrier, so buffer (c+2)%3 == (c-1)%3 is free.
// ===========================================================================
#define BM 128
#define BN 128
#define KCH 32
#define NCHUNK (DM / KCH)  // 32
#define GSTW 20
#define TOFFW 2560
#define GEMM_SMEM 61440

template<int OUTF>
__device__ __forceinline__ void gemm_body(
    const __half* __restrict__ A, const __half* __restrict__ Wt,
    const float* __restrict__ bias, void* __restrict__ Cv, float bscale,
    unsigned* smemw, int m0, int n0)
{
    const unsigned sbase = smem_u32(smemw);
    const int tid = threadIdx.x;
    const int wid = tid >> 5, lane = tid & 31;
    const int g = lane >> 2, tig = lane & 3;
    const int warp_m = wid & 1, warp_n = wid >> 1;
    const int lrow = lane & 7, quad = lane >> 3;

    const int row = tid >> 1;
    const int hc  = (tid & 1) * 16;
    const __half* Aptr = A  + (size_t)(m0 + row) * DM + hc;
    const __half* Bptr = Wt + (size_t)(n0 + row) * DM + hc;
    const unsigned aDst = sbase + (row * GSTW + (tid & 1) * 8) * 4;
    const unsigned bDst = aDst + 3 * TOFFW * 4;

    const unsigned aoffB = ((lrow + 8 * (quad & 1)) * GSTW + 4 * (quad >> 1)) * 4;
    const unsigned boffB = ((lrow + 8 * (quad >> 1)) * GSTW + 4 * (quad & 1)) * 4;

    float acc[4][4][4];
    #pragma unroll
    for (int mt = 0; mt < 4; mt++)
        #pragma unroll
        for (int nt = 0; nt < 4; nt++)
            #pragma unroll
            for (int i = 0; i < 4; i++) acc[mt][nt][i] = 0.f;

    auto stage = [&](int c, int buf) {
        const __half* ap = Aptr + c * KCH;
        const __half* bp = Bptr + c * KCH;
        const unsigned ad = aDst + buf * (TOFFW * 4);
        const unsigned bd = bDst + buf * (TOFFW * 4);
        cp16(ad, ap); cp16(ad + 16, ap + 8);
        cp16(bd, bp); cp16(bd + 16, bp + 8);
    };

    stage(0, 0); CP_COMMIT();
    stage(1, 1); CP_COMMIT();

    for (int c = 0; c < NCHUNK; c++) {
        if (c + 1 < NCHUNK) { CP_WAIT(1); } else { CP_WAIT(0); }
        __syncthreads();
        if (c + 2 < NCHUNK) { stage(c + 2, (c + 2) % 3); CP_COMMIT(); }

        const int buf = c % 3;
        const unsigned abase = sbase + buf * (TOFFW * 4);
        const unsigned bbase = abase + 3 * TOFFW * 4;
        #pragma unroll
        for (int kk = 0; kk < 2; kk++) {
            unsigned af[4][4], bf[4][2];
            #pragma unroll
            for (int mt = 0; mt < 4; mt++) {
                const unsigned ra = abase +
                    ((warp_m * 64 + mt * 16) * GSTW + kk * 8) * 4 + aoffB;
                LDSM4(af[mt][0], af[mt][1], af[mt][2], af[mt][3], ra);
            }
            const unsigned rb0 = bbase + ((warp_n * 32) * GSTW + kk * 8) * 4 + boffB;
            const unsigned rb1 = rb0 + 16 * GSTW * 4;
            LDSM4(bf[0][0], bf[0][1], bf[1][0], bf[1][1], rb0);
            LDSM4(bf[2][0], bf[2][1], bf[3][0], bf[3][1], rb1);
            #pragma unroll
            for (int mt = 0; mt < 4; mt++)
                #pragma unroll
                for (int nt = 0; nt < 4; nt++)
                    mma_f16(acc[mt][nt], af[mt], bf[nt]);
        }
    }

    #pragma unroll
    for (int mt = 0; mt < 4; mt++) {
        const int r0 = m0 + warp_m * 64 + mt * 16 + g;
        #pragma unroll
        for (int nt = 0; nt < 4; nt++) {
            const int col = n0 + warp_n * 32 + nt * 8 + 2 * tig;
            const float bx = bias[col] * bscale, by = bias[col + 1] * bscale;
            if (OUTF) {
                float* C = (float*)Cv;
                float2 v0 = { acc[mt][nt][0] + bx, acc[mt][nt][1] + by };
                float2 v1 = { acc[mt][nt][2] + bx, acc[mt][nt][3] + by };
                *(float2*)&C[(size_t)r0 * DM + col] = v0;
                *(float2*)&C[(size_t)(r0 + 8) * DM + col] = v1;
            } else {
                __half* C = (__half*)Cv;
                *(unsigned*)&C[(size_t)r0 * DM + col] =
                    pack_h2(acc[mt][nt][0] + bx, acc[mt][nt][1] + by);
                *(unsigned*)&C[(size_t)(r0 + 8) * DM + col] =
                    pack_h2(acc[mt][nt][2] + bx, acc[mt][nt][3] + by);
            }
        }
    }
}

__global__ __launch_bounds__(256, 2) void tc_gemm_qkv(
    const __half* __restrict__ A,
    const __half* __restrict__ W0, const __half* __restrict__ W1,
    const __half* __restrict__ W2,
    const float* __restrict__ b0, const float* __restrict__ b1,
    const float* __restrict__ b2,
    __half* __restrict__ C0, __half* __restrict__ C1, __half* __restrict__ C2)
{
    extern __shared__ __align__(16) unsigned smemw[];
    const int z = blockIdx.z;
    const __half* Wt = (z == 0) ? W0 : (z == 1) ? W1 : W2;
    const float* bias = (z == 0) ? b0 : (z == 1) ? b1 : b2;
    __half* C = (z == 0) ? C0 : (z == 1) ? C1 : C2;
    const float bscale = (z == 0) ? 0.125f : 1.f;
    gemm_body<0>(A, Wt, bias, C, bscale, smemw, blockIdx.y * BM, blockIdx.x * BN);
}

__global__ __launch_bounds__(256, 2) void tc_gemm_out(
    const __half* __restrict__ A, const __half* __restrict__ Wt,
    const float* __restrict__ bias, float* __restrict__ C)
{
    extern __shared__ __align__(16) unsigned smemw[];
    gemm_body<1>(A, Wt, bias, C, 1.f, smemw, blockIdx.y * BM, blockIdx.x * BN);
}

// ===========================================================================
// Flash attention (R15 proven): fp16, double-buffered cp.async K/V, ldmatrix
// K frags + ldmatrix.trans V frags, single sync per tile.
// ===========================================================================
#define HST 72   // half stride per row
#define HSW 36   // word stride per row
#define KVBUF (64 * HST)   // halfs per buffer

__global__ __launch_bounds__(256) void flash_h(
    const __half* __restrict__ Q, const __half* __restrict__ K,
    const __half* __restrict__ V, __half* __restrict__ Z)
{
    __shared__ __align__(16) __half ks[2 * KVBUF];
    __shared__ __align__(16) __half vs[2 * KVBUF];
    const unsigned ksb = smem_u32(ks);
    const unsigned vsb = smem_u32(vs);

    const int tid = threadIdx.x;
    const int wid = tid >> 5, lane = tid & 31;
    const int g = lane >> 2, tig = lane & 3;
    const int lrow = lane & 7, quad = lane >> 3;
    const int qt = gridDim.x - 1 - blockIdx.x;       // heavy tiles first
    const int bh = blockIdx.y;
    const int b = bh >> 4, h = bh & 15;
    const size_t base = ((size_t)b * SEQ * NH + h) * DH;
    const int qrow0 = qt * 128 + wid * 16;

    const int srow = tid >> 2;          // staging row 0..63
    const int sc16 = (tid & 3) * 16;    // half offset within 64-half row
    const unsigned kdst = ksb + srow * 144 + (tid & 3) * 32;
    const unsigned vdst = vsb + srow * 144 + (tid & 3) * 32;

    const unsigned kvoffB = ((lrow + 8 * (quad >> 1)) * HSW + 4 * (quad & 1)) * 4;
    const unsigned voffT = ((lane & 15) * HSW + 4 * (lane >> 4)) * 4;

    // ---- Q -> register A-fragments (pre-scaled fp16; 2 cp.async passes) ----
    unsigned aq[4][4];
    #pragma unroll
    for (int pass = 0; pass < 2; pass++) {
        const __half* qp = Q + base + (size_t)(qt * 128 + pass * 64 + srow) * DM + sc16;
        cp16(kdst, qp); cp16(kdst + 16, qp + 8);
        CP_COMMIT(); CP_WAIT(0);
        __syncthreads();
        if ((wid >> 2) == pass) {
            const unsigned aoffB = ((lrow + 8 * (quad & 1)) * HSW + 4 * (quad >> 1)) * 4;
            const int r = (wid & 3) * 16;
            #pragma unroll
            for (int kk = 0; kk < 4; kk++) {
                const unsigned ra = ksb + (r * HSW + kk * 8) * 4 + aoffB;
                LDSM4(aq[kk][0], aq[kk][1], aq[kk][2], aq[kk][3], ra);
            }
        }
        __syncthreads();
    }

    float m0 = -1e30f, m1 = -1e30f, l0 = 0.f, l1 = 0.f;
    float oacc[8][4];
    #pragma unroll
    for (int nt = 0; nt < 8; nt++)
        #pragma unroll
        for (int i = 0; i < 4; i++) oacc[nt][i] = 0.f;

    const int NKT = 2 * qt + 2;

    auto stage_kv = [&](int kt, int buf) {
        const size_t roff = base + (size_t)(kt * 64 + srow) * DM + sc16;
        const unsigned kd = kdst + buf * (KVBUF * 2);
        const unsigned vd = vdst + buf * (KVBUF * 2);
        cp16(kd, K + roff); cp16(kd + 16, K + roff + 8);
        cp16(vd, V + roff); cp16(vd + 16, V + roff + 8);
    };

    stage_kv(0, 0); CP_COMMIT(); CP_WAIT(0);
    __syncthreads();

    for (int kt = 0; kt < NKT; kt++) {
        const int ktb = kt * 64;
        const int buf = kt & 1;
        const bool pre = (kt + 1 < NKT);
        if (pre) { stage_kv(kt + 1, buf ^ 1); CP_COMMIT(); }

        if (ktb <= qrow0 + 15) {
            const unsigned kbase = ksb + buf * (KVBUF * 2) + kvoffB;
            const unsigned vbase = vsb + buf * (KVBUF * 2) + voffT;

            // ---- S = Q K^T ----
            float sacc[8][4];
            #pragma unroll
            for (int nt = 0; nt < 8; nt++)
                #pragma unroll
                for (int i = 0; i < 4; i++) sacc[nt][i] = 0.f;

            #pragma unroll
            for (int kk = 0; kk < 4; kk++) {
                unsigned bf[8][2];
                #pragma unroll
                for (int j = 0; j < 4; j++) {
                    const unsigned rk = kbase + (j * 16 * HSW + kk * 8) * 4;
                    LDSM4(bf[2*j][0], bf[2*j][1], bf[2*j+1][0], bf[2*j+1][1], rk);
                }
                #pragma unroll
                for (int nt = 0; nt < 8; nt++)
                    mma_f16(sacc[nt], aq[kk], bf[nt]);
            }

            // ---- causal mask (diagonal tiles only) ----
            if (ktb + 63 > qrow0) {
                #pragma unroll
                for (int nt = 0; nt < 8; nt++) {
                    const int kv0 = ktb + nt * 8 + 2 * tig;
                    if (kv0     > qrow0 + g)     sacc[nt][0] = -1e30f;
                    if (kv0 + 1 > qrow0 + g)     sacc[nt][1] = -1e30f;
                    if (kv0     > qrow0 + g + 8) sacc[nt][2] = -1e30f;
                    if (kv0 + 1 > qrow0 + g + 8) sacc[nt][3] = -1e30f;
                }
            }

            // ---- online softmax ----
            float rm0 = -1e30f, rm1 = -1e30f;
            #pragma unroll
            for (int nt = 0; nt < 8; nt++) {
                rm0 = fmaxf(rm0, fmaxf(sacc[nt][0], sacc[nt][1]));
                rm1 = fmaxf(rm1, fmaxf(sacc[nt][2], sacc[nt][3]));
            }
            rm0 = fmaxf(rm0, __shfl_xor_sync(0xffffffffu, rm0, 1));
            rm0 = fmaxf(rm0, __shfl_xor_sync(0xffffffffu, rm0, 2));
            rm1 = fmaxf(rm1, __shfl_xor_sync(0xffffffffu, rm1, 1));
            rm1 = fmaxf(rm1, __shfl_xor_sync(0xffffffffu, rm1, 2));
            const float mn0 = fmaxf(m0, rm0), mn1 = fmaxf(m1, rm1);
            const float al0 = __expf(m0 - mn0), al1 = __expf(m1 - mn1);
            float rs0 = 0.f, rs1 = 0.f;
            #pragma unroll
            for (int nt = 0; nt < 8; nt++) {
                sacc[nt][0] = __expf(sacc[nt][0] - mn0); rs0 += sacc[nt][0];
                sacc[nt][1] = __expf(sacc[nt][1] - mn0); rs0 += sacc[nt][1];
                sacc[nt][2] = __expf(sacc[nt][2] - mn1); rs1 += sacc[nt][2];
                sacc[nt][3] = __expf(sacc[nt][3] - mn1); rs1 += sacc[nt][3];
            }
            rs0 += __shfl_xor_sync(0xffffffffu, rs0, 1);
            rs0 += __shfl_xor_sync(0xffffffffu, rs0, 2);
            rs1 += __shfl_xor_sync(0xffffffffu, rs1, 1);
            rs1 += __shfl_xor_sync(0xffffffffu, rs1, 2);
            l0 = l0 * al0 + rs0;  l1 = l1 * al1 + rs1;
            m0 = mn0;             m1 = mn1;
            #pragma unroll
            for (int nt = 0; nt < 8; nt++) {
                oacc[nt][0] *= al0; oacc[nt][1] *= al0;
                oacc[nt][2] *= al1; oacc[nt][3] *= al1;
            }

            // ---- O += P V : P from S regs; V^T frags via ldmatrix.trans ----
            #pragma unroll
            for (int kk = 0; kk < 4; kk++) {
                unsigned ap[4];
                ap[0] = pack_h2(sacc[2*kk][0],   sacc[2*kk][1]);
                ap[1] = pack_h2(sacc[2*kk][2],   sacc[2*kk][3]);
                ap[2] = pack_h2(sacc[2*kk+1][0], sacc[2*kk+1][1]);
                ap[3] = pack_h2(sacc[2*kk+1][2], sacc[2*kk+1][3]);
                unsigned bf[8][2];
                #pragma unroll
                for (int j = 0; j < 4; j++) {
                    const unsigned rv = vbase + (kk * 16 * HSW + j * 8) * 4;
                    LDSM4T(bf[2*j][0], bf[2*j][1], bf[2*j+1][0], bf[2*j+1][1], rv);
                }
                #pragma unroll
                for (int nt = 0; nt < 8; nt++)
                    mma_f16(oacc[nt], ap, bf[nt]);
            }
        }

        if (pre) CP_WAIT(0);
        __syncthreads();
    }

    // ---- normalize + write z (fp16) ----
    const float i0 = 1.f / l0, i1 = 1.f / l1;
    #pragma unroll
    for (int nt = 0; nt < 8; nt++) {
        const int col = nt * 8 + 2 * tig;
        const int row = qrow0 + g;
        *(unsigned*)&Z[base + (size_t)row * DM + col] =
            pack_h2(oacc[nt][0] * i0, oacc[nt][1] * i0);
        *(unsigned*)&Z[base + (size_t)(row + 8) * DM + col] =
            pack_h2(oacc[nt][2] * i1, oacc[nt][3] * i1);
    }
}

// ---------------------------------------------------------------------------

extern "C" void kernel_launch(void* const* d_in, const int* in_sizes, int n_in,
                              void* d_out, int out_size)
{
    const float* x  = (const float*)d_in[0];
    const float* WQ = (const float*)d_in[1];
    const float* WK = (const float*)d_in[2];
    const float* WV = (const float*)d_in[3];
    const float* WO = (const float*)d_in[4];
    const float* bQ = (const float*)d_in[5];
    const float* bK = (const float*)d_in[6];
    const float* bV = (const float*)d_in[7];
    const float* bO = (const float*)d_in[8];
    float* out = (float*)d_out;

    __half *xh, *qh, *kh, *vh, *zh, *wqt, *wkt, *wvt, *wot;
    cudaGetSymbolAddress((void**)&xh,  h_x);
    cudaGetSymbolAddress((void**)&qh,  h_q);
    cudaGetSymbolAddress((void**)&kh,  h_k);
    cudaGetSymbolAddress((void**)&vh,  h_v);
    cudaGetSymbolAddress((void**)&zh,  h_z);
    cudaGetSymbolAddress((void**)&wqt, h_wq);
    cudaGetSymbolAddress((void**)&wkt, h_wk);
    cudaGetSymbolAddress((void**)&wvt, h_wv);
    cudaGetSymbolAddress((void**)&wot, h_wo);

    cudaFuncSetAttribute(tc_gemm_qkv, cudaFuncAttributeMaxDynamicSharedMemorySize, GEMM_SMEM);
    cudaFuncSetAttribute(tc_gemm_out, cudaFuncAttributeMaxDynamicSharedMemorySize, GEMM_SMEM);

    convx_kernel<<<(MTOT * DM) / 4096, 256>>>(x, xh);
    tconv_qkv_kernel<<<dim3(32, 2, 48), dim3(32, 8)>>>(WQ, WK, WV, wqt, wkt, wvt);
    tconv_kernel<<<dim3(32, 32, 1), dim3(32, 8)>>>(WO, wot, DM, DM);

    tc_gemm_qkv<<<dim3(DM / BN, MTOT / BM, 3), 256, GEMM_SMEM>>>(
        xh, wqt, wkt, wvt, bQ, bK, bV, qh, kh, vh);
    flash_h<<<dim3(SEQ / 128, BATCH * NH), 256>>>(qh, kh, vh, zh);
    tc_gemm_out<<<dim3(DM / BN, MTOT / BM), 256, GEMM_SMEM>>>(zh, wot, bO, out);
}